// round 11
// baseline (speedup 1.0000x reference)
#include <cuda_runtime.h>
#include <cuda_bf16.h>
#include <cstdint>

#define NNODES 100000
#define HD 128
#define ROW 640      // 5*HD
#define LMAX 262144

// self-cleaning scratch (consumers zero what they read; first run: zero-init)
__device__ int    g_cnt[2 * NNODES];   // k_count +, k_scan reads then zeroes
__device__ int    g_off[2 * NNODES];   // overwritten by k_scan each run
__device__ int    g_cur[2 * NNODES];   // k_scan inits, k_fuse consumes
__device__ float  g_inv[2 * NNODES];   // overwritten by k_scan each run
// g_sum: [0,1e5) ty*em by s | [1e5,2e5) sm*em by s | [2e5,3e5) ty*dm by d |
//        [3e5,4e5) dm*dm by d.  k_count +, k_fuse reads (sync) then zeroes.
__device__ float  g_sum[4 * NNODES];
// sorted scatter records, 2 float4 each. side0 at [0,L), side1 at [L,2L).
// rec[2p]   = {bits(e), bits(other), bits(slot), x}
// rec[2p+1] = {cm*inv, cb*inv, 0, 0}
__device__ float4 g_rec[4 * LMAX];

// ---------------------------------------------------------------------------
// fast cos: Cody-Waite FMA reduction + cephes minimax polys. |x|<=~1000 here.
// ---------------------------------------------------------------------------
__device__ __forceinline__ float fast_cos(float x) {
    float j = rintf(x * 0.63661977236758134f);
    int   q = (int)j;
    float r = fmaf(j, -1.5707963705062866f, x);
    r = fmaf(j, 4.3711390e-8f, r);
    float r2 = r * r;
    float ps = fmaf(r2, -1.9515295891e-4f, 8.3321608736e-3f);
    ps = fmaf(r2, ps, -1.6666654611e-1f);
    float s  = fmaf(r * r2, ps, r);
    float pc = fmaf(r2, 2.443315711809948e-5f, -1.388731625493765e-3f);
    pc = fmaf(r2, pc, 4.166664568298827e-2f);
    pc = fmaf(r2, pc, -0.5f);
    float c  = fmaf(r2, pc, 1.0f);
    float v = (q & 1) ? s : c;
    if ((q + 1) & 2) v = -v;
    return v;
}

// ---------------------------------------------------------------------------
// 1) per-event counts + factored scalar sums
// ---------------------------------------------------------------------------
__global__ void k_count(const int* __restrict__ type, const int* __restrict__ src,
                        const float* __restrict__ sm, const int* __restrict__ dst,
                        const float* __restrict__ dm, const float* __restrict__ em,
                        int L) {
    int i = blockIdx.x * blockDim.x + threadIdx.x;
    if (i >= L) return;
    int   s   = src[i], d = dst[i];
    float smv = sm[i], dmv = dm[i], emv = em[i];
    float ty  = (float)type[i];
    atomicAdd(&g_cnt[s], 1);
    atomicAdd(&g_cnt[NNODES + d], 1);
    atomicAdd(&g_sum[s],               ty * emv);
    atomicAdd(&g_sum[NNODES + s],      smv * emv);
    atomicAdd(&g_sum[2 * NNODES + d],  ty * dmv);
    atomicAdd(&g_sum[3 * NNODES + d],  dmv * dmv);
}

// ---------------------------------------------------------------------------
// 2) exclusive scan -> offsets; inverse counts; init cursors; zero g_cnt.
// ---------------------------------------------------------------------------
__global__ void k_scan() {
    const int base  = blockIdx.x * NNODES;
    const int chunk = (NNODES + 1023) / 1024;
    int t  = threadIdx.x;
    int s0 = t * chunk;
    int s1 = min(s0 + chunk, NNODES);
    int sum = 0;
    for (int i = s0; i < s1; i++) sum += g_cnt[base + i];
    __shared__ int sh[1024];
    sh[t] = sum;
    __syncthreads();
    for (int d = 1; d < 1024; d <<= 1) {
        int v = 0;
        if (t >= d) v = sh[t - d];
        __syncthreads();
        if (t >= d) sh[t] += v;
        __syncthreads();
    }
    int excl = (t == 0) ? 0 : sh[t - 1];
    for (int i = s0; i < s1; i++) {
        int c = g_cnt[base + i];
        g_off[base + i] = excl;
        g_cur[base + i] = 0;
        g_inv[base + i] = 1.0f / (float)max(c, 1);
        g_cnt[base + i] = 0;          // self-clean for next run
        excl += c;
    }
}

// ---------------------------------------------------------------------------
// 3) fused: blocks [0,FB) build sorted records; blocks [FB,FB+NNODES) write
//    factored blocks 0-1 + zero blocks 2-4 of both rows, then (after a
//    barrier!) self-clean the scalar sums.
// ---------------------------------------------------------------------------
__global__ void __launch_bounds__(128)
k_fuse(const int* __restrict__ type, const int* __restrict__ src,
       const float* __restrict__ sm, const int* __restrict__ dst,
       const float* __restrict__ dm, const float* __restrict__ em,
       const float* __restrict__ ts, const float* __restrict__ lu,
       const float* __restrict__ mem, float* __restrict__ out,
       int L, int FB) {
    if (blockIdx.x < (unsigned)FB) {
        int i = blockIdx.x * 128 + threadIdx.x;
        if (i >= L) return;
        int   s   = src[i], d = dst[i];
        float smv = sm[i], dmv = dm[i], emv = em[i], t = ts[i];
        float lus = __ldg(lu + s), lud = __ldg(lu + d);
        float inv_s = g_inv[s], inv_d = g_inv[NNODES + d];

        // src side: slot = s, cb = event_mask (faithful: lu*dst_mask both sides)
        int p = atomicAdd(&g_cur[s], 1) + g_off[s];
        g_rec[2 * p]     = make_float4(__int_as_float(i), __int_as_float(d),
                                       __int_as_float(s), t - lus * dmv);
        g_rec[2 * p + 1] = make_float4(dmv * emv * inv_s, emv * inv_s, 0.f, 0.f);

        // dst side: slot = NNODES+d, cb = dst_mask
        p = L + atomicAdd(&g_cur[NNODES + d], 1) + g_off[NNODES + d];
        g_rec[2 * p]     = make_float4(__int_as_float(i), __int_as_float(s),
                                       __int_as_float(NNODES + d), t - lud * dmv);
        g_rec[2 * p + 1] = make_float4(smv * dmv * inv_d, dmv * inv_d, 0.f, 0.f);
    } else {
        int n = blockIdx.x - FB;
        int h = threadIdx.x;
        float inv_s = g_inv[n], inv_d = g_inv[NNODES + n];
        float a0s = g_sum[n]              * inv_s;
        float c1s = g_sum[NNODES + n]     * inv_s;
        float a0d = g_sum[2 * NNODES + n] * inv_d;
        float c1d = g_sum[3 * NNODES + n] * inv_d;
        __syncthreads();   // ALL warps must finish reading g_sum before clean
        if (h < 4) g_sum[h * NNODES + n] = 0.0f;   // self-clean
        float mv = __ldg(mem + (size_t)n * HD + h);
        float* os = out + (size_t)n * ROW;
        float* od = out + (size_t)(NNODES + n) * ROW;
        os[h] = a0s;  os[128 + h] = mv * c1s;
        os[256 + h] = 0.f; os[384 + h] = 0.f; os[512 + h] = 0.f;
        od[h] = a0d;  od[128 + h] = mv * c1d;
        od[256 + h] = 0.f; od[384 + h] = 0.f; od[512 + h] = 0.f;
    }
}

// ---------------------------------------------------------------------------
// 4) sorted scatter: one warp per sorted record. Consecutive warps hit the
//    same / neighboring output rows -> atomic RMW stays in L2. Lane l owns
//    h = l + 32k, each atomicAdd is one coalesced 128B line.
// ---------------------------------------------------------------------------
__global__ void __launch_bounds__(256)
k_scatter(const float* __restrict__ E, const float* __restrict__ M,
          const float* __restrict__ w, const float* __restrict__ b,
          float* __restrict__ out, int nrec) {
    int wid  = (blockIdx.x * blockDim.x + threadIdx.x) >> 5;
    int lane = threadIdx.x & 31;
    if (wid >= nrec) return;

    float4 ra = __ldg(&g_rec[2 * wid]);
    float4 rb = __ldg(&g_rec[2 * wid + 1]);
    int   e     = __float_as_int(ra.x);
    int   other = __float_as_int(ra.y);
    int   slot  = __float_as_int(ra.z);
    float x     = ra.w;
    float cm = rb.x, cb = rb.y;

    const float* erow = E + (size_t)e * HD;
    const float* mrow = M + (size_t)other * HD;
    float*       o    = out + (size_t)slot * ROW;

#pragma unroll
    for (int k = 0; k < 4; k++) {
        int h = lane + 32 * k;
        float wv = __ldg(w + h), bv = __ldg(b + h);
        float Ev = __ldg(erow + h);
        float Mv = __ldg(mrow + h);
        atomicAdd(o + 256 + h, Mv * cm);
        atomicAdd(o + 384 + h, fast_cos(fmaf(x, wv, bv)) * cb);
        atomicAdd(o + 512 + h, Ev * cb);
    }
}

// ---------------------------------------------------------------------------
extern "C" void kernel_launch(void* const* d_in, const int* in_sizes, int n_in,
                              void* d_out, int out_size) {
    const int*   type = (const int*)  d_in[0];
    const int*   src  = (const int*)  d_in[1];
    const float* smk  = (const float*)d_in[2];
    const int*   dst  = (const int*)  d_in[3];
    const float* dmk  = (const float*)d_in[4];
    const float* E    = (const float*)d_in[5];
    const float* em   = (const float*)d_in[6];
    const float* ts   = (const float*)d_in[7];
    const float* mem  = (const float*)d_in[8];
    const float* lu   = (const float*)d_in[9];
    const float* w    = (const float*)d_in[10];
    const float* b    = (const float*)d_in[11];
    float* out = (float*)d_out;
    int L = in_sizes[0];
    if (L > LMAX) L = LMAX;
    int FB = (L + 127) / 128;

    k_count<<<(L + 255) / 256, 256>>>(type, src, smk, dst, dmk, em, L);
    k_scan <<<2, 1024>>>();
    k_fuse <<<FB + NNODES, 128>>>(type, src, smk, dst, dmk, em, ts, lu, mem,
                                  out, L, FB);
    int nrec = 2 * L;
    k_scatter<<<(nrec * 32 + 255) / 256, 256>>>(E, mem, w, b, out, nrec);
}

// round 12
// speedup vs baseline: 2.8544x; 2.8544x over previous
#include <cuda_runtime.h>
#include <cuda_bf16.h>
#include <cstdint>

#define NNODES 100000
#define HD 128
#define ROW 640      // 5*HD
#define LMAX 262144
#define SBLK 98      // ceil(100000/1024) scan blocks per side

// scratch (self-cleaning across graph replays; zero-init at load)
__device__ int    g_cnt [2 * NNODES];  // k_count +, scanA reads then zeroes
__device__ int    g_cnt2[2 * NNODES];  // snapshot for gather
__device__ int    g_off [2 * NNODES];
__device__ int    g_cur [2 * NNODES];
__device__ float  g_inv [2 * NNODES];
__device__ int    g_bsum[2 * SBLK];
__device__ int    g_boff[2 * SBLK];
// sorted per-(side,position) event records: 2 float4s each.
// rec[2p+0] = {bits(e), bits(other), s0, c1}   rec[2p+1] = {cm, cb, x, pad}
__device__ float4 g_rec[4 * LMAX];

// ---------------------------------------------------------------------------
// fast cos: Cody-Waite FMA reduction + cephes minimax polys. |x|<=~1000 here.
// ---------------------------------------------------------------------------
__device__ __forceinline__ float fast_cos(float x) {
    float j = rintf(x * 0.63661977236758134f);
    int   q = (int)j;
    float r = fmaf(j, -1.5707963705062866f, x);
    r = fmaf(j, 4.3711390e-8f, r);
    float r2 = r * r;
    float ps = fmaf(r2, -1.9515295891e-4f, 8.3321608736e-3f);
    ps = fmaf(r2, ps, -1.6666654611e-1f);
    float s  = fmaf(r * r2, ps, r);
    float pc = fmaf(r2, 2.443315711809948e-5f, -1.388731625493765e-3f);
    pc = fmaf(r2, pc, 4.166664568298827e-2f);
    pc = fmaf(r2, pc, -0.5f);
    float c  = fmaf(r2, pc, 1.0f);
    float v = (q & 1) ? s : c;
    if ((q + 1) & 2) v = -v;
    return v;
}

// ---------------------------------------------------------------------------
__global__ void k_count(const int* __restrict__ src, const int* __restrict__ dst,
                        int L) {
    int i = blockIdx.x * blockDim.x + threadIdx.x;
    if (i >= L) return;
    atomicAdd(&g_cnt[src[i]], 1);
    atomicAdd(&g_cnt[NNODES + dst[i]], 1);
}

// ---------------------------------------------------------------------------
// scanA: coalesced block-local exclusive scan (1024/block), per side.
// Also snapshots counts, inits cursors/inv, self-cleans g_cnt.
// ---------------------------------------------------------------------------
__global__ void __launch_bounds__(1024)
k_scanA() {
    __shared__ int sh[1024];
    int side = blockIdx.y;
    int gid  = blockIdx.x * 1024 + threadIdx.x;
    int idx  = side * NNODES + gid;
    bool ok  = gid < NNODES;
    int c = ok ? g_cnt[idx] : 0;
    sh[threadIdx.x] = c;
    __syncthreads();
    for (int d = 1; d < 1024; d <<= 1) {
        int t = (threadIdx.x >= d) ? sh[threadIdx.x - d] : 0;
        __syncthreads();
        sh[threadIdx.x] += t;
        __syncthreads();
    }
    if (ok) {
        g_off [idx] = sh[threadIdx.x] - c;   // exclusive within block
        g_cnt2[idx] = c;
        g_inv [idx] = 1.0f / (float)max(c, 1);
        g_cur [idx] = 0;
        g_cnt [idx] = 0;                     // self-clean for next replay
    }
    if (threadIdx.x == 1023) g_bsum[side * SBLK + blockIdx.x] = sh[1023];
}

// scanB: one block scans the 98 block sums of each side (exclusive).
__global__ void k_scanB() {
    __shared__ int sh[2][128];
    int tid  = threadIdx.x;          // 256 threads
    int side = tid >> 7, j = tid & 127;
    int v = (j < SBLK) ? g_bsum[side * SBLK + j] : 0;
    sh[side][j] = v;
    __syncthreads();
    for (int d = 1; d < 128; d <<= 1) {
        int t = (j >= d) ? sh[side][j - d] : 0;
        __syncthreads();
        sh[side][j] += t;
        __syncthreads();
    }
    if (j < SBLK) g_boff[side * SBLK + j] = sh[side][j] - v;
}

// scanC: add block offsets (coalesced).
__global__ void __launch_bounds__(1024)
k_scanC() {
    int side = blockIdx.y;
    int gid  = blockIdx.x * 1024 + threadIdx.x;
    if (gid >= NNODES) return;
    g_off[side * NNODES + gid] += g_boff[side * SBLK + blockIdx.x];
}

// ---------------------------------------------------------------------------
// counting-sort fill: write fully-precomputed records at sorted positions.
// ---------------------------------------------------------------------------
__global__ void k_fill(const int* __restrict__ type, const int* __restrict__ src,
                       const float* __restrict__ sm, const int* __restrict__ dst,
                       const float* __restrict__ dm, const float* __restrict__ em,
                       const float* __restrict__ ts, const float* __restrict__ lu,
                       int L) {
    int i = blockIdx.x * blockDim.x + threadIdx.x;
    if (i >= L) return;
    int   s   = src[i], d = dst[i];
    float smv = sm[i], dmv = dm[i], emv = em[i], t = ts[i];
    float ty  = (float)type[i];
    float lus = __ldg(lu + s), lud = __ldg(lu + d);

    // src side: message scale cb = event_mask
    int p = atomicAdd(&g_cur[s], 1) + g_off[s];
    g_rec[2 * p]     = make_float4(__int_as_float(i), __int_as_float(d),
                                   ty * emv, smv * emv);
    g_rec[2 * p + 1] = make_float4(dmv * emv, emv, t - lus * dmv, 0.0f);

    // dst side: cb = dst_mask (faithful: lu*dst_mask both sides)
    p = atomicAdd(&g_cur[NNODES + d], 1) + g_off[NNODES + d] + LMAX;
    g_rec[2 * p]     = make_float4(__int_as_float(i), __int_as_float(s),
                                   ty * dmv, dmv * dmv);
    g_rec[2 * p + 1] = make_float4(smv * dmv, dmv, t - lud * dmv, 0.0f);
}

// ---------------------------------------------------------------------------
// gather: one warp per (side,node), lane l owns h = 4l..4l+3 (float4 rows).
// Software-pipelined over the node's sorted records; row written exactly once.
// ---------------------------------------------------------------------------
__global__ void __launch_bounds__(256)
k_gather(const float4* __restrict__ E4, const float4* __restrict__ M4,
         const float4* __restrict__ W4, const float4* __restrict__ B4,
         float4* __restrict__ out4) {
    int gw   = (blockIdx.x * blockDim.x + threadIdx.x) >> 5;
    int lane = threadIdx.x & 31;
    if (gw >= 2 * NNODES) return;
    int  slot  = gw;
    bool dside = slot >= NNODES;
    int  n     = dside ? slot - NNODES : slot;

    int   off = g_off[slot] + (dside ? LMAX : 0);
    int   cnt = g_cnt2[slot];
    float inv = g_inv[slot];
    float4 wv = __ldg(W4 + lane), bv = __ldg(B4 + lane);

    float  a0 = 0.f, a1 = 0.f;
    float4 a2 = make_float4(0, 0, 0, 0);
    float4 a3 = make_float4(0, 0, 0, 0);
    float4 a4 = make_float4(0, 0, 0, 0);

    float4 ra = make_float4(0, 0, 0, 0), rb = ra;
    if (cnt > 0) { ra = __ldg(g_rec + 2 * off); rb = __ldg(g_rec + 2 * off + 1); }
    for (int j = 0; j < cnt; j++) {
        float4 ra_n = ra, rb_n = rb;
        if (j + 1 < cnt) {
            ra_n = __ldg(g_rec + 2 * (off + j + 1));
            rb_n = __ldg(g_rec + 2 * (off + j + 1) + 1);
        }
        int   e     = __float_as_int(ra.x);
        int   other = __float_as_int(ra.y);
        float cm = rb.x, cb = rb.y, x = rb.z;
        float4 Ev = __ldg(E4 + (size_t)e * 32 + lane);
        float4 Mv = __ldg(M4 + (size_t)other * 32 + lane);
        a0 += ra.z;
        a1 += ra.w;
        a2.x = fmaf(Mv.x, cm, a2.x); a2.y = fmaf(Mv.y, cm, a2.y);
        a2.z = fmaf(Mv.z, cm, a2.z); a2.w = fmaf(Mv.w, cm, a2.w);
        a3.x = fmaf(fast_cos(fmaf(x, wv.x, bv.x)), cb, a3.x);
        a3.y = fmaf(fast_cos(fmaf(x, wv.y, bv.y)), cb, a3.y);
        a3.z = fmaf(fast_cos(fmaf(x, wv.z, bv.z)), cb, a3.z);
        a3.w = fmaf(fast_cos(fmaf(x, wv.w, bv.w)), cb, a3.w);
        a4.x = fmaf(Ev.x, cb, a4.x); a4.y = fmaf(Ev.y, cb, a4.y);
        a4.z = fmaf(Ev.z, cb, a4.z); a4.w = fmaf(Ev.w, cb, a4.w);
        ra = ra_n; rb = rb_n;
    }

    float4 Mn = __ldg(M4 + (size_t)n * 32 + lane);
    float  b0 = a0 * inv, b1 = a1 * inv;
    float4* o = out4 + (size_t)slot * 160;   // 640/4
    o[lane]       = make_float4(b0, b0, b0, b0);
    o[32 + lane]  = make_float4(Mn.x * b1, Mn.y * b1, Mn.z * b1, Mn.w * b1);
    o[64 + lane]  = make_float4(a2.x * inv, a2.y * inv, a2.z * inv, a2.w * inv);
    o[96 + lane]  = make_float4(a3.x * inv, a3.y * inv, a3.z * inv, a3.w * inv);
    o[128 + lane] = make_float4(a4.x * inv, a4.y * inv, a4.z * inv, a4.w * inv);
}

// ---------------------------------------------------------------------------
extern "C" void kernel_launch(void* const* d_in, const int* in_sizes, int n_in,
                              void* d_out, int out_size) {
    const int*   type = (const int*)  d_in[0];
    const int*   src  = (const int*)  d_in[1];
    const float* smk  = (const float*)d_in[2];
    const int*   dst  = (const int*)  d_in[3];
    const float* dmk  = (const float*)d_in[4];
    const float* E    = (const float*)d_in[5];
    const float* em   = (const float*)d_in[6];
    const float* ts   = (const float*)d_in[7];
    const float* mem  = (const float*)d_in[8];
    const float* lu   = (const float*)d_in[9];
    const float* w    = (const float*)d_in[10];
    const float* b    = (const float*)d_in[11];
    float* out = (float*)d_out;
    int L = in_sizes[0];
    if (L > LMAX) L = LMAX;

    dim3 sgrid(SBLK, 2);
    k_count<<<(L + 255) / 256, 256>>>(src, dst, L);
    k_scanA<<<sgrid, 1024>>>();
    k_scanB<<<1, 256>>>();
    k_scanC<<<sgrid, 1024>>>();
    k_fill <<<(L + 255) / 256, 256>>>(type, src, smk, dst, dmk, em, ts, lu, L);

    int warps = 2 * NNODES;
    k_gather<<<(warps * 32 + 255) / 256, 256>>>(
        (const float4*)E, (const float4*)mem, (const float4*)w,
        (const float4*)b, (float4*)out);
}

// round 14
// speedup vs baseline: 3.0046x; 1.0526x over previous
#include <cuda_runtime.h>
#include <cuda_bf16.h>
#include <cstdint>

#define NNODES 100000
#define HD 128
#define ROW 640      // 5*HD
#define LMAX 262144
#define SBLK 98      // ceil(100000/1024) scan blocks per side

// scratch (self-cleaning across graph replays; zero-init at load)
__device__ int    g_cnt [2 * NNODES];  // k_count +, scanA reads then zeroes
__device__ int    g_cnt2[2 * NNODES];  // snapshot (scanA)
__device__ int    g_off [2 * NNODES];
__device__ int    g_cur [2 * NNODES];
__device__ float  g_inv [2 * NNODES];
__device__ float4 g_hdr [2 * NNODES];  // {bits(off), bits(cnt), inv, 0} (scanC)
__device__ int    g_bsum[2 * SBLK];
__device__ int    g_boff[2 * SBLK];
// sorted per-(side,position) event records: 2 float4s each.
// rec[2p+0] = {bits(e), bits(other), s0, c1}   rec[2p+1] = {cm, cb, x, pad}
__device__ float4 g_rec[4 * LMAX];

// ---------------------------------------------------------------------------
// fast cos: Cody-Waite FMA reduction + cephes minimax polys. |x|<=~1000 here.
// ---------------------------------------------------------------------------
__device__ __forceinline__ float fast_cos(float x) {
    float j = rintf(x * 0.63661977236758134f);
    int   q = (int)j;
    float r = fmaf(j, -1.5707963705062866f, x);
    r = fmaf(j, 4.3711390e-8f, r);
    float r2 = r * r;
    float ps = fmaf(r2, -1.9515295891e-4f, 8.3321608736e-3f);
    ps = fmaf(r2, ps, -1.6666654611e-1f);
    float s  = fmaf(r * r2, ps, r);
    float pc = fmaf(r2, 2.443315711809948e-5f, -1.388731625493765e-3f);
    pc = fmaf(r2, pc, 4.166664568298827e-2f);
    pc = fmaf(r2, pc, -0.5f);
    float c  = fmaf(r2, pc, 1.0f);
    float v = (q & 1) ? s : c;
    if ((q + 1) & 2) v = -v;
    return v;
}

// ---------------------------------------------------------------------------
__global__ void k_count(const int* __restrict__ src, const int* __restrict__ dst,
                        int L) {
    int i = blockIdx.x * blockDim.x + threadIdx.x;
    if (i >= L) return;
    atomicAdd(&g_cnt[src[i]], 1);
    atomicAdd(&g_cnt[NNODES + dst[i]], 1);
}

// ---------------------------------------------------------------------------
// scanA: coalesced block-local exclusive scan (1024/block), per side.
// Also snapshots counts, inits cursors/inv, self-cleans g_cnt.
// ---------------------------------------------------------------------------
__global__ void __launch_bounds__(1024)
k_scanA() {
    __shared__ int sh[1024];
    int side = blockIdx.y;
    int gid  = blockIdx.x * 1024 + threadIdx.x;
    int idx  = side * NNODES + gid;
    bool ok  = gid < NNODES;
    int c = ok ? g_cnt[idx] : 0;
    sh[threadIdx.x] = c;
    __syncthreads();
    for (int d = 1; d < 1024; d <<= 1) {
        int t = (threadIdx.x >= d) ? sh[threadIdx.x - d] : 0;
        __syncthreads();
        sh[threadIdx.x] += t;
        __syncthreads();
    }
    if (ok) {
        g_off [idx] = sh[threadIdx.x] - c;   // exclusive within block
        g_cnt2[idx] = c;
        g_inv [idx] = 1.0f / (float)max(c, 1);
        g_cur [idx] = 0;
        g_cnt [idx] = 0;                     // self-clean for next replay
    }
    if (threadIdx.x == 1023) g_bsum[side * SBLK + blockIdx.x] = sh[1023];
}

// scanB: one block scans the 98 block sums of each side (exclusive).
__global__ void k_scanB() {
    __shared__ int sh[2][128];
    int tid  = threadIdx.x;          // 256 threads
    int side = tid >> 7, j = tid & 127;
    int v = (j < SBLK) ? g_bsum[side * SBLK + j] : 0;
    sh[side][j] = v;
    __syncthreads();
    for (int d = 1; d < 128; d <<= 1) {
        int t = (j >= d) ? sh[side][j - d] : 0;
        __syncthreads();
        sh[side][j] += t;
        __syncthreads();
    }
    if (j < SBLK) g_boff[side * SBLK + j] = sh[side][j] - v;
}

// scanC: add block offsets (coalesced) + emit packed per-slot header.
__global__ void __launch_bounds__(1024)
k_scanC() {
    int side = blockIdx.y;
    int gid  = blockIdx.x * 1024 + threadIdx.x;
    if (gid >= NNODES) return;
    int idx = side * NNODES + gid;
    int off = g_off[idx] + g_boff[side * SBLK + blockIdx.x];
    g_off[idx] = off;
    g_hdr[idx] = make_float4(__int_as_float(off), __int_as_float(g_cnt2[idx]),
                             g_inv[idx], 0.0f);
}

// ---------------------------------------------------------------------------
// counting-sort fill: write fully-precomputed records at sorted positions.
// ---------------------------------------------------------------------------
__global__ void k_fill(const int* __restrict__ type, const int* __restrict__ src,
                       const float* __restrict__ sm, const int* __restrict__ dst,
                       const float* __restrict__ dm, const float* __restrict__ em,
                       const float* __restrict__ ts, const float* __restrict__ lu,
                       int L) {
    int i = blockIdx.x * blockDim.x + threadIdx.x;
    if (i >= L) return;
    int   s   = src[i], d = dst[i];
    float smv = sm[i], dmv = dm[i], emv = em[i], t = ts[i];
    float ty  = (float)type[i];
    float lus = __ldg(lu + s), lud = __ldg(lu + d);

    // src side: message scale cb = event_mask
    int p = atomicAdd(&g_cur[s], 1) + g_off[s];
    g_rec[2 * p]     = make_float4(__int_as_float(i), __int_as_float(d),
                                   ty * emv, smv * emv);
    g_rec[2 * p + 1] = make_float4(dmv * emv, emv, t - lus * dmv, 0.0f);

    // dst side: cb = dst_mask (faithful: lu*dst_mask both sides)
    p = atomicAdd(&g_cur[NNODES + d], 1) + g_off[NNODES + d] + LMAX;
    g_rec[2 * p]     = make_float4(__int_as_float(i), __int_as_float(s),
                                   ty * dmv, dmv * dmv);
    g_rec[2 * p + 1] = make_float4(smv * dmv, dmv, t - lud * dmv, 0.0f);
}

// ---------------------------------------------------------------------------
// gather: one warp per (side,node), lane l owns h = 4l..4l+3 (float4 rows).
// E rows streamed (__ldcs, touched once); mem table left in L2 (reused);
// output written once with __stcs (evict-first). Row written exactly once.
// ---------------------------------------------------------------------------
__global__ void __launch_bounds__(256)
k_gather(const float4* __restrict__ E4, const float4* __restrict__ M4,
         const float4* __restrict__ W4, const float4* __restrict__ B4,
         float4* __restrict__ out4) {
    int gw   = (blockIdx.x * blockDim.x + threadIdx.x) >> 5;
    int lane = threadIdx.x & 31;
    if (gw >= 2 * NNODES) return;
    int  slot  = gw;
    bool dside = slot >= NNODES;
    int  n     = dside ? slot - NNODES : slot;

    float4 hdr = __ldg(&g_hdr[slot]);
    int   off  = __float_as_int(hdr.x) + (dside ? LMAX : 0);
    int   cnt  = __float_as_int(hdr.y);
    float inv  = hdr.z;
    float4 wv = __ldg(W4 + lane), bv = __ldg(B4 + lane);

    float  a0 = 0.f, a1 = 0.f;
    float4 a2 = make_float4(0, 0, 0, 0);
    float4 a3 = make_float4(0, 0, 0, 0);
    float4 a4 = make_float4(0, 0, 0, 0);

    float4 ra = make_float4(0, 0, 0, 0), rb = ra;
    if (cnt > 0) { ra = __ldg(g_rec + 2 * off); rb = __ldg(g_rec + 2 * off + 1); }
    for (int j = 0; j < cnt; j++) {
        float4 ra_n = ra, rb_n = rb;
        if (j + 1 < cnt) {
            ra_n = __ldg(g_rec + 2 * (off + j + 1));
            rb_n = __ldg(g_rec + 2 * (off + j + 1) + 1);
        }
        int   e     = __float_as_int(ra.x);
        int   other = __float_as_int(ra.y);
        float cm = rb.x, cb = rb.y, x = rb.z;
        float4 Ev = __ldcs(E4 + (size_t)e * 32 + lane);     // streamed
        float4 Mv = __ldg (M4 + (size_t)other * 32 + lane); // L2-resident
        a0 += ra.z;
        a1 += ra.w;
        a2.x = fmaf(Mv.x, cm, a2.x); a2.y = fmaf(Mv.y, cm, a2.y);
        a2.z = fmaf(Mv.z, cm, a2.z); a2.w = fmaf(Mv.w, cm, a2.w);
        a3.x = fmaf(fast_cos(fmaf(x, wv.x, bv.x)), cb, a3.x);
        a3.y = fmaf(fast_cos(fmaf(x, wv.y, bv.y)), cb, a3.y);
        a3.z = fmaf(fast_cos(fmaf(x, wv.z, bv.z)), cb, a3.z);
        a3.w = fmaf(fast_cos(fmaf(x, wv.w, bv.w)), cb, a3.w);
        a4.x = fmaf(Ev.x, cb, a4.x); a4.y = fmaf(Ev.y, cb, a4.y);
        a4.z = fmaf(Ev.z, cb, a4.z); a4.w = fmaf(Ev.w, cb, a4.w);
        ra = ra_n; rb = rb_n;
    }

    float4 Mn = __ldg(M4 + (size_t)n * 32 + lane);
    float  b0 = a0 * inv, b1 = a1 * inv;
    float4* o = out4 + (size_t)slot * 160;   // 640/4
    __stcs(o + lane,       make_float4(b0, b0, b0, b0));
    __stcs(o + 32 + lane,  make_float4(Mn.x * b1, Mn.y * b1, Mn.z * b1, Mn.w * b1));
    __stcs(o + 64 + lane,  make_float4(a2.x * inv, a2.y * inv, a2.z * inv, a2.w * inv));
    __stcs(o + 96 + lane,  make_float4(a3.x * inv, a3.y * inv, a3.z * inv, a3.w * inv));
    __stcs(o + 128 + lane, make_float4(a4.x * inv, a4.y * inv, a4.z * inv, a4.w * inv));
}

// ---------------------------------------------------------------------------
extern "C" void kernel_launch(void* const* d_in, const int* in_sizes, int n_in,
                              void* d_out, int out_size) {
    const int*   type = (const int*)  d_in[0];
    const int*   src  = (const int*)  d_in[1];
    const float* smk  = (const float*)d_in[2];
    const int*   dst  = (const int*)  d_in[3];
    const float* dmk  = (const float*)d_in[4];
    const float* E    = (const float*)d_in[5];
    const float* em   = (const float*)d_in[6];
    const float* ts   = (const float*)d_in[7];
    const float* mem  = (const float*)d_in[8];
    const float* lu   = (const float*)d_in[9];
    const float* w    = (const float*)d_in[10];
    const float* b    = (const float*)d_in[11];
    float* out = (float*)d_out;
    int L = in_sizes[0];
    if (L > LMAX) L = LMAX;

    dim3 sgrid(SBLK, 2);
    k_count<<<(L + 255) / 256, 256>>>(src, dst, L);
    k_scanA<<<sgrid, 1024>>>();
    k_scanB<<<1, 256>>>();
    k_scanC<<<sgrid, 1024>>>();
    k_fill <<<(L + 255) / 256, 256>>>(type, src, smk, dst, dmk, em, ts, lu, L);

    int warps = 2 * NNODES;
    k_gather<<<(warps * 32 + 255) / 256, 256>>>(
        (const float4*)E, (const float4*)mem, (const float4*)w,
        (const float4*)b, (float4*)out);
}